// round 3
// baseline (speedup 1.0000x reference)
#include <cuda_runtime.h>

// BatchSRU: L=2048, B=8, D=128, NB=16  (fp32)
// One persistent CTA per (b,nb). W[nb] resident in SMEM. 256 threads:
//   j = tid & 127  -> output channel (and load lane k=j for x staging)
//   s = tid >> 7   -> time-slice: slice s computes timesteps [s*8, s*8+8) of a
//                     16-step time block. Dot phase fully parallel; the 16-step
//                     scan is serialized slice0 -> slice1 via a 1-float SMEM handoff.
// Inner dot loop per k: 12x fma.rn.f32x2 (time-pairs), 2x LDS.128 (x pairs),
// 1x LDS.64 (Wx/Wf interleaved), 1x LDS.32 (Wr).

#define L_SEQ 2048
#define BATCH 8
#define DIM   128
#define NBI   16
#define TBLK  16
#define XSTRIDE (BATCH * DIM * NBI)   // 16384 floats per timestep

typedef unsigned long long u64;

__device__ __forceinline__ u64 pack2(float lo, float hi) {
    u64 r; asm("mov.b64 %0, {%1, %2};" : "=l"(r) : "f"(lo), "f"(hi)); return r;
}
__device__ __forceinline__ void unpack2(u64 v, float& lo, float& hi) {
    asm("mov.b64 {%0, %1}, %2;" : "=f"(lo), "=f"(hi) : "l"(v));
}
__device__ __forceinline__ void fma2(u64& d, u64 a, u64 b) {
    asm("fma.rn.f32x2 %0, %1, %2, %0;" : "+l"(d) : "l"(a), "l"(b));
}
__device__ __forceinline__ float sigmoidf_fast(float z) {
    return __fdividef(1.0f, 1.0f + __expf(-z));
}

// SMEM layout (float offsets):
//   Wxf : float2[128k][128j]  -> 32768 floats (131072 B)
//   Wr  : float [128k][128j]  -> 16384 floats
//   xs  : ulonglong2[4 qgroups][128 k] (= 16 floats per k) -> 2048 floats
//   cprev[128], cmid[128]
#define OFF_WXF 0
#define OFF_WR  32768
#define OFF_XS  49152
#define OFF_CP  51200
#define OFF_CM  51328
#define SMEM_BYTES ((51456) * 4)      // 205824 B

__global__ void __launch_bounds__(256, 1) batch_sru_kernel(
    const float* __restrict__ x,
    const float* __restrict__ W,
    const float* __restrict__ bias,
    float* __restrict__ out)
{
    extern __shared__ float smem[];
    const int tid = threadIdx.x;
    const int j   = tid & 127;        // channel
    const int s   = tid >> 7;         // time slice (0 or 1)
    const int b   = blockIdx.x >> 4;
    const int nb  = blockIdx.x & 15;

    float2* Wxf = (float2*)(smem + OFF_WXF);
    float*  Wr  = smem + OFF_WR;
    ulonglong2* xs2 = (ulonglong2*)(smem + OFF_XS);
    float* cprev = smem + OFF_CP;
    float* cmid  = smem + OFF_CM;

    // ---- One-time: load W[nb] (128 x 384 row-major) into Wxf/Wr
    {
        const float4* Wg4 = (const float4*)(W + (size_t)nb * (DIM * 3 * DIM));
        #pragma unroll 4
        for (int idx = tid; idx < (DIM * 3 * DIM) / 4; idx += 256) {
            float4 v = Wg4[idx];
            int e  = idx * 4;
            int k  = e / 384;
            int h  = e - k * 384;
            int g  = h >> 7;
            int jj = h & 127;
            float vv[4] = {v.x, v.y, v.z, v.w};
            #pragma unroll
            for (int i = 0; i < 4; i++) {
                if (g == 0)      Wxf[k * 128 + jj + i].x = vv[i];
                else if (g == 1) Wxf[k * 128 + jj + i].y = vv[i];
                else             Wr [k * 128 + jj + i]   = vv[i];
            }
        }
    }
    if (tid < 128) cprev[tid] = 0.0f;

    const float bfv = bias[nb * 256 + j];
    const float brv = bias[nb * 256 + 128 + j];

    // x element for (t, b, k=j, nb)
    const int xbase = (b * DIM + j) * NBI + nb;
    float* outp = out + xbase;                 // + t*XSTRIDE

    // Prefetch this thread's 8 timesteps of block 0 (t = s*8 + tt)
    float xv[8];
    #pragma unroll
    for (int tt = 0; tt < 8; tt++)
        xv[tt] = x[(s * 8 + tt) * XSTRIDE + xbase];

    const int q0 = (s * 2) * 128;              // ulonglong2 group indices
    const int q1 = (s * 2 + 1) * 128;

    for (int t0 = 0; t0 < L_SEQ; t0 += TBLK) {
        // ---- Stage current block's x into SMEM (pairs packed as u64)
        {
            ulonglong2 pa, pb;
            pa.x = pack2(xv[0], xv[1]); pa.y = pack2(xv[2], xv[3]);
            pb.x = pack2(xv[4], xv[5]); pb.y = pack2(xv[6], xv[7]);
            xs2[q0 + j] = pa;
            xs2[q1 + j] = pb;
        }
        __syncthreads();                       // (b) xs + W + cprev visible

        float xcur[8];
        #pragma unroll
        for (int tt = 0; tt < 8; tt++) xcur[tt] = xv[tt];

        // Prefetch next block (hidden under the dot phase)
        if (t0 + TBLK < L_SEQ) {
            #pragma unroll
            for (int tt = 0; tt < 8; tt++)
                xv[tt] = x[(t0 + TBLK + s * 8 + tt) * XSTRIDE + xbase];
        }

        // ---- Dot phase: 3 gates x 8 timesteps (4 time-pairs), f32x2 FMAs
        u64 aX[4], aF[4], aR[4];
        #pragma unroll
        for (int p = 0; p < 4; p++) { aX[p] = 0ull; aF[p] = 0ull; aR[p] = 0ull; }

        #pragma unroll 8
        for (int k = 0; k < DIM; k++) {
            ulonglong2 xa = xs2[q0 + k];       // pairs 0,1 of this slice
            ulonglong2 xb = xs2[q1 + k];       // pairs 2,3
            float2 wxf = Wxf[k * 128 + j];
            float  wr  = Wr [k * 128 + j];
            u64 wx2 = pack2(wxf.x, wxf.x);
            u64 wf2 = pack2(wxf.y, wxf.y);
            u64 wr2 = pack2(wr,    wr);
            fma2(aX[0], wx2, xa.x); fma2(aX[1], wx2, xa.y);
            fma2(aX[2], wx2, xb.x); fma2(aX[3], wx2, xb.y);
            fma2(aF[0], wf2, xa.x); fma2(aF[1], wf2, xa.y);
            fma2(aF[2], wf2, xb.x); fma2(aF[3], wf2, xb.y);
            fma2(aR[0], wr2, xa.x); fma2(aR[1], wr2, xa.y);
            fma2(aR[2], wr2, xb.x); fma2(aR[3], wr2, xb.y);
        }

        // ---- Gates (both slices in parallel; pipelines the MUFU work)
        float xt[8], fp[8], rp[8];
        #pragma unroll
        for (int p = 0; p < 4; p++) {
            unpack2(aX[p], xt[2*p], xt[2*p+1]);
            unpack2(aF[p], fp[2*p], fp[2*p+1]);
            unpack2(aR[p], rp[2*p], rp[2*p+1]);
        }
        float fv[8], rv[8];
        #pragma unroll
        for (int t = 0; t < 8; t++) {
            fv[t] = sigmoidf_fast(fp[t] + bfv);
            rv[t] = sigmoidf_fast(rp[t] + brv);
        }

        // ---- Scan: slice 0 does t0..t0+7, hands c to slice 1 for t0+8..t0+15
        if (s == 0) {
            float c = cprev[j];
            #pragma unroll
            for (int t = 0; t < 8; t++) {
                c = fmaf(fv[t], c - xt[t], xt[t]);             // f*c + (1-f)*xt
                float h = fmaf(rv[t], c - xcur[t], xcur[t]);   // r*c + (1-r)*x
                outp[(t0 + t) * XSTRIDE] = h;
            }
            cmid[j] = c;
        }
        __syncthreads();                       // (c) cmid ready
        if (s == 1) {
            float c = cmid[j];
            #pragma unroll
            for (int t = 0; t < 8; t++) {
                c = fmaf(fv[t], c - xt[t], xt[t]);
                float h = fmaf(rv[t], c - xcur[t], xcur[t]);
                outp[(t0 + 8 + t) * XSTRIDE] = h;
            }
            cprev[j] = c;                      // consumed after next barrier
        }
        // next iteration's xs store is safe: all xs reads completed before (c)
    }
}

extern "C" void kernel_launch(void* const* d_in, const int* in_sizes, int n_in,
                              void* d_out, int out_size) {
    const float* x  = (const float*)d_in[0];
    const float* W  = (const float*)d_in[1];
    const float* bi = (const float*)d_in[2];
    float* out = (float*)d_out;

    cudaFuncSetAttribute(batch_sru_kernel,
                         cudaFuncAttributeMaxDynamicSharedMemorySize, SMEM_BYTES);
    batch_sru_kernel<<<BATCH * NBI, 256, SMEM_BYTES>>>(x, W, bi, out);
}

// round 5
// speedup vs baseline: 1.7814x; 1.7814x over previous
#include <cuda_runtime.h>
#include <cuda_bf16.h>
#include <cuda_fp16.h>
#include <cstdint>

// BatchSRU: L=2048, B=8, D=128, NB=16, fp32. Legacy HMMA path (mma.sync bf16),
// since ptxas target is sm_103 base (no tcgen05).
//  Pass 1: transpose x (L,B,D,NB) -> x'[b][nb][t][k] (coalesced main-kernel reads)
//  Pass 2: 1 CTA per (b,nb). W^T resident in SMEM as bf16 hi/lo.
//          Per 16-step tile: U[h][t] = sum_k W[k][h] x[t][k] via m16n8k16 bf16
//          mma.sync, fp32 emulated with 3 hi/lo combos. Then warps 0-3 scan
//          (c thread-local in a register), warps 4-7 stage the next x tile.

#define L_SEQ 2048
#define BATCH 8
#define DIM   128
#define NBI   16
#define NT    16
#define NTILES (L_SEQ / NT)
#define XSTRIDE 16384

__device__ float g_xT[L_SEQ * BATCH * DIM * NBI];   // 134 MB scratch

// ---- main-kernel SMEM byte offsets (rows are 256B, XOR-swizzled 16B chunks)
#define OFF_WHI 0            // 384 x 256
#define OFF_WLO 98304        // 384 x 256
#define OFF_XB  196608       // 2 bufs x (hi 4096 + lo 4096)
#define OFF_UX  212992       // fp32 [16t][128h]
#define OFF_UF  221184       // fp16 [16t][128h]
#define OFF_UR  225280       // fp16 [16t][128h]
#define SMEM_MAIN 229376

__device__ __forceinline__ uint32_t smem_u32(const void* p) {
    uint32_t a;
    asm("{ .reg .u64 t; cvta.to.shared.u64 t, %1; cvt.u32.u64 %0, t; }" : "=r"(a) : "l"(p));
    return a;
}
__device__ __forceinline__ void ldsm_x4(uint32_t* r, uint32_t addr) {
    asm volatile("ldmatrix.sync.aligned.m8n8.x4.shared.b16 {%0,%1,%2,%3}, [%4];"
                 : "=r"(r[0]), "=r"(r[1]), "=r"(r[2]), "=r"(r[3]) : "r"(addr));
}
__device__ __forceinline__ void ldsm_x2(uint32_t* r, uint32_t addr) {
    asm volatile("ldmatrix.sync.aligned.m8n8.x2.shared.b16 {%0,%1}, [%2];"
                 : "=r"(r[0]), "=r"(r[1]) : "r"(addr));
}
__device__ __forceinline__ void mma_bf16(float* d, const uint32_t* a, const uint32_t* b) {
    asm volatile("mma.sync.aligned.m16n8k16.row.col.f32.bf16.bf16.f32 "
                 "{%0,%1,%2,%3}, {%4,%5,%6,%7}, {%8,%9}, {%0,%1,%2,%3};"
                 : "+f"(d[0]), "+f"(d[1]), "+f"(d[2]), "+f"(d[3])
                 : "r"(a[0]), "r"(a[1]), "r"(a[2]), "r"(a[3]), "r"(b[0]), "r"(b[1]));
}
__device__ __forceinline__ float sigf(float z) {
    return __fdividef(1.0f, 1.0f + __expf(-z));
}
// pack 2 floats to bf16x2 (hi), return residuals
__device__ __forceinline__ uint32_t packbf(float a, float b, float& la, float& lb) {
    __nv_bfloat162 h = __floats2bfloat162_rn(a, b);
    la = a - __low2float(h);
    lb = b - __high2float(h);
    return *(uint32_t*)&h;
}
__device__ __forceinline__ uint32_t packbf2(float a, float b) {
    __nv_bfloat162 h = __floats2bfloat162_rn(a, b);
    return *(uint32_t*)&h;
}

// ================= Pass 1: transpose x -> g_xT [b][nb][t][k] =================
#define TP_T 4
__global__ void __launch_bounds__(256) transpose_x(const float* __restrict__ x) {
    __shared__ float sm[TP_T * 16 * 129];
    const int bx = blockIdx.x;            // (t-chunk)*8 + b
    const int t0 = (bx >> 3) * TP_T;
    const int b  = bx & 7;
    #pragma unroll 4
    for (int i = 0; i < 32; i++) {
        int idx  = i * 256 + threadIdx.x;        // 0..8191
        int tloc = idx >> 11;
        int rem  = idx & 2047;                   // k*16 + nb
        int k = rem >> 4, nb = rem & 15;
        float v = x[((size_t)(t0 + tloc) * BATCH + b) * (DIM * NBI) + rem];
        sm[(tloc * 16 + nb) * 129 + k] = v;
    }
    __syncthreads();
    #pragma unroll 4
    for (int i = 0; i < 32; i++) {
        int idx = i * 256 + threadIdx.x;
        int k = idx & 127;
        int chunk = idx >> 7;                    // nb*4 + tloc
        int nb = chunk >> 2, tloc = chunk & 3;
        g_xT[(((size_t)(b * NBI + nb)) * L_SEQ + t0 + tloc) * DIM + k] =
            sm[(tloc * 16 + nb) * 129 + k];
    }
}

// ================= Pass 2: main =================
__global__ void __launch_bounds__(256, 1) sru_main(
    const float* __restrict__ W, const float* __restrict__ bias,
    float* __restrict__ out)
{
    extern __shared__ char sm[];
    const uint32_t sb = smem_u32(sm);
    const int tid  = threadIdx.x;
    const int lane = tid & 31;
    const int w    = tid >> 5;
    const int bx = blockIdx.x, b = bx >> 4, nb = bx & 15;

    // ---- stage W^T hi/lo into swizzled SMEM rows (one-time)
    {
        const float* Wp = W + (size_t)nb * (DIM * 3 * DIM);
        #pragma unroll 4
        for (int it = 0; it < 192; it++) {
            int idx = it * 256 + tid;            // = k*384 + h
            int k = idx / 384, h = idx - k * 384;
            float v = Wp[idx];
            __nv_bfloat16 hi = __float2bfloat16(v);
            __nv_bfloat16 lo = __float2bfloat16(v - __bfloat162float(hi));
            uint32_t byt = (uint32_t)h * 256 + ((((k >> 3) ^ (h & 15)) << 4)) + ((k & 7) * 2);
            *(__nv_bfloat16*)(sm + OFF_WHI + byt) = hi;
            *(__nv_bfloat16*)(sm + OFF_WLO + byt) = lo;
        }
    }
    // ---- stage x tile 0 into buf 0 (all threads, 8 floats each = one 16B chunk)
    {
        int t = tid >> 4, cc = tid & 15;
        const float4* src = (const float4*)(g_xT + ((size_t)bx * L_SEQ + t) * DIM + cc * 8);
        float4 v0 = src[0], v1 = src[1];
        float l0, l1, l2, l3, l4, l5, l6, l7;
        uint4 H, L;
        H.x = packbf(v0.x, v0.y, l0, l1);  H.y = packbf(v0.z, v0.w, l2, l3);
        H.z = packbf(v1.x, v1.y, l4, l5);  H.w = packbf(v1.z, v1.w, l6, l7);
        L.x = packbf2(l0, l1); L.y = packbf2(l2, l3);
        L.z = packbf2(l4, l5); L.w = packbf2(l6, l7);
        uint32_t a = OFF_XB + (uint32_t)t * 256 + ((cc ^ t) << 4);
        *(uint4*)(sm + a)        = H;
        *(uint4*)(sm + a + 4096) = L;
    }
    const int j = tid & 127;
    const float bfv = bias[nb * 256 + j];
    const float brv = bias[nb * 256 + 128 + j];
    float* outp = out + ((size_t)(b * DIM + j)) * NBI + nb;
    float c = 0.0f;
    __syncthreads();

    // lane-fixed ldmatrix address components
    const int a_tile = lane >> 3;                 // 0..3
    const int a_row_add = (lane & 7) + ((a_tile & 1) << 3);
    const int a_chalf   = a_tile >> 1;            // +chunk for k-high half
    const int b_row     = (lane & 7);             // B tile row (t within ntile)
    const int b_chalf   = (lane >> 3) & 1;
    const int g  = lane >> 2;
    const int tg = lane & 3;
    const int s  = tid - 128;                     // staging thread id (warps 4-7)

    for (int i = 0; i < NTILES; i++) {
        const int buf = i & 1;
        // prefetch next tile into regs (staging warps), overlaps GEMM
        float4 pf0, pf1, pf2, pf3;
        if (w >= 4 && i + 1 < NTILES) {
            const float4* src = (const float4*)
                (g_xT + ((size_t)bx * L_SEQ + (size_t)(i + 1) * NT) * DIM) + s * 4;
            pf0 = src[0]; pf1 = src[1]; pf2 = src[2]; pf3 = src[3];
        }

        // ---------- phase A: GEMM (all 8 warps; warp w owns mtiles 3w..3w+2)
        float D[3][2][4];
        #pragma unroll
        for (int mi = 0; mi < 3; mi++)
            #pragma unroll
            for (int nt = 0; nt < 2; nt++)
                #pragma unroll
                for (int e = 0; e < 4; e++) D[mi][nt][e] = 0.0f;

        const uint32_t xb_hi = sb + OFF_XB + buf * 8192;
        #pragma unroll
        for (int ks = 0; ks < 8; ks++) {
            uint32_t Bhi[2][2], Blo[2][2];
            #pragma unroll
            for (int nt = 0; nt < 2; nt++) {
                int trow = nt * 8 + b_row;
                uint32_t ba = xb_hi + trow * 256 + (((2 * ks + b_chalf) ^ trow) << 4);
                ldsm_x2(Bhi[nt], ba);
                ldsm_x2(Blo[nt], ba + 4096);
            }
            #pragma unroll
            for (int mi = 0; mi < 3; mi++) {
                int mt = w * 3 + mi;
                int row = mt * 16 + a_row_add;
                uint32_t aa = sb + OFF_WHI + row * 256 +
                              (((2 * ks + a_chalf) ^ (row & 15)) << 4);
                uint32_t Ahi[4], Alo[4];
                ldsm_x4(Ahi, aa);
                ldsm_x4(Alo, aa + (OFF_WLO - OFF_WHI));
                #pragma unroll
                for (int nt = 0; nt < 2; nt++) {
                    mma_bf16(D[mi][nt], Ahi, Bhi[nt]);
                    mma_bf16(D[mi][nt], Alo, Bhi[nt]);
                    mma_bf16(D[mi][nt], Ahi, Blo[nt]);
                }
            }
        }
        // store U: gate 0 (x_tilde) fp32, gates 1,2 fp16
        #pragma unroll
        for (int mi = 0; mi < 3; mi++) {
            int mt = w * 3 + mi;
            int gate = mt >> 3;
            int h0 = (mt & 7) * 16 + g;
            #pragma unroll
            for (int nt = 0; nt < 2; nt++) {
                int t0 = nt * 8 + tg * 2;
                if (gate == 0) {
                    float* u = (float*)(sm + OFF_UX);
                    u[(t0)     * DIM + h0]     = D[mi][nt][0];
                    u[(t0 + 1) * DIM + h0]     = D[mi][nt][1];
                    u[(t0)     * DIM + h0 + 8] = D[mi][nt][2];
                    u[(t0 + 1) * DIM + h0 + 8] = D[mi][nt][3];
                } else {
                    __half* u = (__half*)(sm + (gate == 1 ? OFF_UF : OFF_UR));
                    u[(t0)     * DIM + h0]     = __float2half_rn(D[mi][nt][0]);
                    u[(t0 + 1) * DIM + h0]     = __float2half_rn(D[mi][nt][1]);
                    u[(t0)     * DIM + h0 + 8] = __float2half_rn(D[mi][nt][2]);
                    u[(t0 + 1) * DIM + h0 + 8] = __float2half_rn(D[mi][nt][3]);
                }
            }
        }
        __syncthreads();

        // ---------- phase B: scan (warps 0-3) | stage next tile (warps 4-7)
        if (w < 4) {
            const float* ux = (const float*)(sm + OFF_UX);
            const __half* uf = (const __half*)(sm + OFF_UF);
            const __half* ur = (const __half*)(sm + OFF_UR);
            float* op = outp + (size_t)i * NT * XSTRIDE;
            #pragma unroll
            for (int t = 0; t < NT; t++) {
                float xt = ux[t * DIM + j];
                float fv = sigf(__half2float(uf[t * DIM + j]) + bfv);
                float rv = sigf(__half2float(ur[t * DIM + j]) + brv);
                c = fmaf(fv, c - xt, xt);
                uint32_t xa = OFF_XB + buf * 8192 + t * 256 +
                              (((j >> 3) ^ t) << 4) + ((j & 7) * 2);
                float xv = __bfloat162float(*(__nv_bfloat16*)(sm + xa)) +
                           __bfloat162float(*(__nv_bfloat16*)(sm + xa + 4096));
                op[(size_t)t * XSTRIDE] = fmaf(rv, c - xv, xv);
            }
        } else if (i + 1 < NTILES) {
            int t = s >> 3, c0 = (s & 7) * 2;
            float v[16] = {pf0.x, pf0.y, pf0.z, pf0.w, pf1.x, pf1.y, pf1.z, pf1.w,
                           pf2.x, pf2.y, pf2.z, pf2.w, pf3.x, pf3.y, pf3.z, pf3.w};
            uint32_t H[8], L[8];
            #pragma unroll
            for (int p = 0; p < 8; p++) {
                float la, lb;
                H[p] = packbf(v[2 * p], v[2 * p + 1], la, lb);
                L[p] = packbf2(la, lb);
            }
            uint32_t base = OFF_XB + (1 - buf) * 8192 + (uint32_t)t * 256;
            uint32_t a0 = base + ((c0 ^ t) << 4);
            uint32_t a1 = base + (((c0 + 1) ^ t) << 4);
            *(uint4*)(sm + a0) = make_uint4(H[0], H[1], H[2], H[3]);
            *(uint4*)(sm + a1) = make_uint4(H[4], H[5], H[6], H[7]);
            *(uint4*)(sm + a0 + 4096) = make_uint4(L[0], L[1], L[2], L[3]);
            *(uint4*)(sm + a1 + 4096) = make_uint4(L[4], L[5], L[6], L[7]);
        }
        __syncthreads();
    }
}

extern "C" void kernel_launch(void* const* d_in, const int* in_sizes, int n_in,
                              void* d_out, int out_size) {
    const float* x  = (const float*)d_in[0];
    const float* W  = (const float*)d_in[1];
    const float* bi = (const float*)d_in[2];
    float* out = (float*)d_out;

    transpose_x<<<(L_SEQ / TP_T) * BATCH, 256>>>(x);
    cudaFuncSetAttribute(sru_main, cudaFuncAttributeMaxDynamicSharedMemorySize, SMEM_MAIN);
    sru_main<<<BATCH * NBI, 256, SMEM_MAIN>>>(W, bi, out);
}